// round 7
// baseline (speedup 1.0000x reference)
#include <cuda_runtime.h>
#include <math.h>

// ---------------- problem constants ----------------
#define B_  8
#define N_  2048
#define D_  16
#define K_  8
#define SCALE_ 0.35355339059327373f     // hd^-0.5
#define LOG2E_ 1.4426950408889634f

typedef unsigned long long ull;

// ---------------- packed f32x2 helpers ----------------
#define FMA2(d, a, b, c) asm("fma.rn.f32x2 %0, %1, %2, %3;" : "=l"(d) : "l"(a), "l"(b), "l"(c))
__device__ __forceinline__ ull pack2(float lo, float hi) {
    ull r; asm("mov.b64 %0, {%1, %2};" : "=l"(r) : "f"(lo), "f"(hi)); return r;
}
__device__ __forceinline__ void unpack2(ull v, float& lo, float& hi) {
    asm("mov.b64 {%0, %1}, %2;" : "=f"(lo), "=f"(hi) : "l"(v));
}
__device__ __forceinline__ float ex2f(float x) {
    float r; asm("ex2.approx.f32 %0, %1;" : "=f"(r) : "f"(x)); return r;
}
__device__ __forceinline__ float rcpf(float x) {
    float r; asm("rcp.approx.f32 %0, %1;" : "=f"(r) : "f"(x)); return r;
}
// tanh(x) = 1 - 2/(exp(2x)+1), exp via ex2
__device__ __forceinline__ float fast_tanh(float x) {
    float e = ex2f(2.8853900817779268f * x);
    return fmaf(-2.f, rcpf(e + 1.f), 1.f);
}

// ---------------- scratch ----------------
__device__ float g_Q   [B_ * N_ * 32];
__device__ float g_Kt  [B_ * N_ * 32];
__device__ float g_att [B_ * N_ * D_];
__device__ float g_wsumAcc[B_ * D_];
__device__ float g_hypf[B_ * K_ * D_];
__device__ float g_fimraw[B_ * K_];

// ---------------- Cl(3,0,1) helpers ----------------
__device__ __forceinline__ float cayley_sign(int a, int b) {
    int neg = 0;
#pragma unroll
    for (int i = 0; i < 4; i++)
        if ((b >> i) & 1) neg ^= (__popc(a >> (i + 1)) & 1);
    if ((a & b) & 8) return 0.f;
    return neg ? -1.f : 1.f;
}
__device__ __forceinline__ float rev_sign(int i) {
    int p = __popc(i);
    return ((p * (p - 1) / 2) & 1) ? -1.f : 1.f;
}

// ---------------- kernel 1: Q/K projection (+ init) ----------------
__global__ __launch_bounds__(128) void proj_kernel(const float* __restrict__ state,
                            const float* __restrict__ Wq, const float* __restrict__ bq,
                            const float* __restrict__ Wk, const float* __restrict__ bk,
                            const float* __restrict__ hyp,
                            const float* __restrict__ W_hyp,
                            const float* __restrict__ b_hyp) {
    __shared__ __align__(16) float sWq[16][32], sWk[16][32], sbq[32], sbk[32];
    int t = threadIdx.x;
    if (blockIdx.x == 0) {
        if (t < B_ * K_) g_fimraw[t] = 0.f;
        if (t < B_ * D_) g_wsumAcc[t] = 0.f;
        for (int i = t; i < B_ * K_ * D_; i += 128) {
            int bk_ = i >> 4, d = i & 15;
            float v = b_hyp[d];
#pragma unroll
            for (int c = 0; c < 4; c++) v = fmaf(hyp[bk_ * 4 + c], W_hyp[c * D_ + d], v);
            g_hypf[i] = v;
        }
    }
    for (int i = t; i < 512; i += 128) { sWq[i >> 5][i & 31] = Wq[i]; sWk[i >> 5][i & 31] = Wk[i]; }
    if (t < 32) { sbq[t] = bq[t]; sbk[t] = bk[t]; }
    __syncthreads();
    size_t row = (size_t)blockIdx.x * 128 + t;
    float s[16];
    const float4* sp = (const float4*)(state + row * 16);
#pragma unroll
    for (int i = 0; i < 4; i++) { float4 v = sp[i]; s[4*i]=v.x; s[4*i+1]=v.y; s[4*i+2]=v.z; s[4*i+3]=v.w; }
    ull sd[16];
#pragma unroll
    for (int d = 0; d < 16; d++) sd[d] = pack2(s[d], s[d]);
    ull* qo = (ull*)(g_Q  + row * 32);
    ull* ko = (ull*)(g_Kt + row * 32);
#pragma unroll
    for (int c2 = 0; c2 < 16; c2++) {
        ull aq = ((const ull*)sbq)[c2];
        ull ak = ((const ull*)sbk)[c2];
#pragma unroll
        for (int d = 0; d < 16; d++) {
            FMA2(aq, sd[d], ((const ull*)&sWq[d][0])[c2], aq);
            FMA2(ak, sd[d], ((const ull*)&sWk[d][0])[c2], ak);
        }
        qo[c2] = aq; ko[c2] = ak;
    }
}

// ---------------- kernel 2: fused attention + fim (128 rows/block, 256 thr) ----------------
#define TM_ 128
__global__ __launch_bounds__(256, 1) void attn_kernel(const float* __restrict__ state,
                                                      const float* __restrict__ v_gains,
                                                      const float* __restrict__ W_act,
                                                      const float* __restrict__ b_act) {
    int b    = blockIdx.y;
    int t    = threadIdx.x;
    int head = t & 3;
    int g    = t >> 2;                         // 0..63
    int n0   = blockIdx.x * 128 + g * 2;

    __shared__ __align__(16) float Ks[TM_][32];
    __shared__ __align__(16) float Ss[TM_][16];
    __shared__ __align__(16) float sWa[K_][16][16];
    __shared__ __align__(16) float sAb[K_][16];
    __shared__ float sW[8][16];
    __shared__ float sFim[8][8];

    // stage W_act + (b_act + hypf)
    for (int i = t; i < 2048; i += 256) sWa[i >> 8][(i >> 4) & 15][i & 15] = W_act[i];
    if (t < 128) sAb[t >> 4][t & 15] = b_act[t] + g_hypf[b * 128 + t];

    // q prescaled into log2 domain
    const float qs = SCALE_ * LOG2E_;
    ull q[2][4];
#pragma unroll
    for (int r = 0; r < 2; r++) {
        const float4* qp = (const float4*)(g_Q + ((size_t)b * N_ + n0 + r) * 32 + head * 8);
        float4 a = qp[0], c = qp[1];
        q[r][0] = pack2(a.x * qs, a.y * qs);
        q[r][1] = pack2(a.z * qs, a.w * qs);
        q[r][2] = pack2(c.x * qs, c.y * qs);
        q[r][3] = pack2(c.z * qs, c.w * qs);
    }
    ull o[2][8];
#pragma unroll
    for (int r = 0; r < 2; r++)
#pragma unroll
        for (int j = 0; j < 8; j++) o[r][j] = 0ULL;
    float l0 = 0.f, l1 = 0.f;

    for (int m0 = 0; m0 < N_; m0 += TM_) {
        __syncthreads();
#pragma unroll
        for (int i = 0; i < 4; i++) {
            int idx = t + i * 256;             // Ks: 1024 float4
            int r = idx >> 3, c = idx & 7;
            ((float4*)&Ks[r][0])[c] = ((const float4*)(g_Kt + ((size_t)b * N_ + m0 + r) * 32))[c];
        }
#pragma unroll
        for (int i = 0; i < 2; i++) {
            int idx = t + i * 256;             // Ss: 512 float4
            int r = idx >> 2, c = idx & 3;
            ((float4*)&Ss[r][0])[c] = ((const float4*)(state + ((size_t)b * N_ + m0 + r) * 16))[c];
        }
        __syncthreads();
#pragma unroll 4
        for (int mm = 0; mm < TM_; mm++) {
            const ulonglong2* kp = (const ulonglong2*)&Ks[mm][head * 8];
            ulonglong2 ka = kp[0], kb = kp[1];
            const ulonglong2* vp = (const ulonglong2*)&Ss[mm][0];
            ulonglong2 va = vp[0], vb = vp[1], vc = vp[2], vd = vp[3];
#pragma unroll
            for (int r = 0; r < 2; r++) {
                ull acc;
                FMA2(acc, q[r][0], ka.x, 0ULL);
                FMA2(acc, q[r][1], ka.y, acc);
                FMA2(acc, q[r][2], kb.x, acc);
                FMA2(acc, q[r][3], kb.y, acc);
                float lo, hi; unpack2(acc, lo, hi);
                float p = ex2f(lo + hi);       // exp in log2 domain, no clamp
                if (r == 0) l0 += p; else l1 += p;
                ull pp = pack2(p, p);
                FMA2(o[r][0], pp, va.x, o[r][0]);
                FMA2(o[r][1], pp, va.y, o[r][1]);
                FMA2(o[r][2], pp, vb.x, o[r][2]);
                FMA2(o[r][3], pp, vb.y, o[r][3]);
                FMA2(o[r][4], pp, vc.x, o[r][4]);
                FMA2(o[r][5], pp, vc.y, o[r][5]);
                FMA2(o[r][6], pp, vd.x, o[r][6]);
                FMA2(o[r][7], pp, vd.y, o[r][7]);
            }
        }
    }

    // ---- epilogue: head combine + write + wsum + fim ----
    float gain = 0.25f * v_gains[0];
    float wacc[16];
#pragma unroll
    for (int d = 0; d < 16; d++) wacc[d] = 0.f;
    float ssk0 = 0.f, ssk1 = 0.f;
    int k0 = head << 1;
#pragma unroll
    for (int r = 0; r < 2; r++) {
        float inv = rcpf(r == 0 ? l0 : l1);
        float ov[16];
#pragma unroll
        for (int j = 0; j < 8; j++) unpack2(o[r][j], ov[2*j], ov[2*j+1]);
#pragma unroll
        for (int d = 0; d < 16; d++) {
            float v = ov[d] * inv;
            v += __shfl_xor_sync(0xffffffffu, v, 1);
            v += __shfl_xor_sync(0xffffffffu, v, 2);
            v *= gain;
            ov[d] = v;
            wacc[d] += v;
        }
        if (head == 0) {
            float4* ap = (float4*)(g_att + ((size_t)b * N_ + n0 + r) * 16);
#pragma unroll
            for (int i = 0; i < 4; i++)
                ap[i] = make_float4(ov[4*i], ov[4*i+1], ov[4*i+2], ov[4*i+3]);
        }
        // fim contribution for this row, hypotheses k0 and k0+1
        ull av[16];
#pragma unroll
        for (int d = 0; d < 16; d++) av[d] = pack2(ov[d], ov[d]);
#pragma unroll
        for (int kk = 0; kk < 2; kk++) {
            int k = k0 + kk;
            ull acc[8];
#pragma unroll
            for (int e2 = 0; e2 < 8; e2++) acc[e2] = ((const ull*)&sAb[k][0])[e2];
#pragma unroll
            for (int d = 0; d < 16; d++) {
                const ull* wr = (const ull*)&sWa[k][d][0];
#pragma unroll
                for (int e2 = 0; e2 < 8; e2++) FMA2(acc[e2], av[d], wr[e2], acc[e2]);
            }
            float ss = 0.f;
#pragma unroll
            for (int e2 = 0; e2 < 8; e2++) {
                float v0, v1; unpack2(acc[e2], v0, v1);
                v0 = fast_tanh(v0); v1 = fast_tanh(v1);
                ss = fmaf(v0, v0, fmaf(v1, v1, ss));
            }
            if (kk) ssk1 += ss; else ssk0 += ss;
        }
    }
    // wsum reduce (quads: bits 2-4)
#pragma unroll
    for (int d = 0; d < 16; d++) {
        float v = wacc[d];
        v += __shfl_xor_sync(0xffffffffu, v, 4);
        v += __shfl_xor_sync(0xffffffffu, v, 8);
        v += __shfl_xor_sync(0xffffffffu, v, 16);
        wacc[d] = v;
    }
    if ((t & 31) == 0) {
#pragma unroll
        for (int d = 0; d < 16; d++) sW[t >> 5][d] = wacc[d];
    }
    // fim reduce over g-lanes (bits 2-4), head lanes keep their k-pair
    ssk0 += __shfl_xor_sync(0xffffffffu, ssk0, 4);
    ssk0 += __shfl_xor_sync(0xffffffffu, ssk0, 8);
    ssk0 += __shfl_xor_sync(0xffffffffu, ssk0, 16);
    ssk1 += __shfl_xor_sync(0xffffffffu, ssk1, 4);
    ssk1 += __shfl_xor_sync(0xffffffffu, ssk1, 8);
    ssk1 += __shfl_xor_sync(0xffffffffu, ssk1, 16);
    if ((t & 31) < 4) {
        int w = t >> 5;
        sFim[w][k0]     = ssk0;
        sFim[w][k0 + 1] = ssk1;
    }
    __syncthreads();
    if (t < 16) {
        float s = 0.f;
#pragma unroll
        for (int w = 0; w < 8; w++) s += sW[w][t];
        atomicAdd(&g_wsumAcc[b * 16 + t], s);
    } else if (t >= 32 && t < 40) {
        int k = t - 32;
        float s = 0.f;
#pragma unroll
        for (int w = 0; w < 8; w++) s += sFim[w][k];
        atomicAdd(&g_fimraw[b * 8 + k], s * (1.f / 16.f));
    }
}

// ---------------- kernel 3: fused small-math + candidate recompute + gates + norm ----------------
__global__ __launch_bounds__(128) void final_kernel(const float* __restrict__ state,
                            const float* __restrict__ hyp, const float* __restrict__ R_accum,
                            const float* __restrict__ W_ws, const float* __restrict__ b_ws,
                            const float* __restrict__ W_s1, const float* __restrict__ b_s1,
                            const float* __restrict__ W_s2, const float* __restrict__ b_s2,
                            const float* __restrict__ W_lift, const float* __restrict__ b_lift,
                            const float* __restrict__ rotors,
                            const float* __restrict__ W_act, const float* __restrict__ b_act,
                            const float* __restrict__ Wg1, const float* __restrict__ bg1,
                            const float* __restrict__ Wg2, const float* __restrict__ bg2,
                            const float* __restrict__ Wc1, const float* __restrict__ bc1,
                            const float* __restrict__ Wc2, const float* __restrict__ bc2,
                            const float* __restrict__ norm_scale,
                            float* __restrict__ out_ns, float* __restrict__ out_newhyp,
                            float* __restrict__ out_R, float* __restrict__ out_fim,
                            float* __restrict__ out_w, float* __restrict__ out_gate) {
    int b = blockIdx.y;
    int bx = blockIdx.x;
    int t = threadIdx.x;
    int n = bx * 128 + t;

    __shared__ __align__(16) float sWg1[32][64];
    __shared__ __align__(16) float sWg2[64][16];
    __shared__ __align__(16) float sWa[K_][16][16];
    __shared__ __align__(16) float sAb[K_][16];
    __shared__ __align__(16) float sbg1[64], sbg2[16];
    __shared__ float sWc1[2][16], sbc1[16], sWc2[16], sns[16];
    __shared__ float sW1[640], sW2[320];
    __shared__ float sC[256];
    __shared__ float s_nh[8][4], s_logit[8], s_fim[8];
    __shared__ float s_w[8], s_agg[4], s_mod[16];
    __shared__ float s_Rt[16], s_Racc[16], s_Rn[16];
    __shared__ float sbc2, s_g0;

    // ---- stage weights ----
    for (int i = t; i < 2048; i += 128) sWg1[i >> 6][i & 63] = Wg1[i];
    for (int i = t; i < 1024; i += 128) sWg2[i >> 4][i & 15] = Wg2[i];
    for (int i = t; i < 2048; i += 128) sWa[i >> 8][(i >> 4) & 15][i & 15] = W_act[i];
    for (int i = t; i < 640; i += 128) sW1[i] = W_s1[i];
    for (int i = t; i < 320; i += 128) sW2[i] = W_s2[i];
    for (int i = t; i < 256; i += 128) sC[i] = cayley_sign(i >> 4, i & 15);
    if (t < 128) sAb[t >> 4][t & 15] = b_act[t] + g_hypf[b * 128 + t];
    if (t < 64) sbg1[t] = bg1[t];
    if (t < 16) { sbg2[t] = bg2[t]; sbc1[t] = bc1[t]; sWc2[t] = Wc2[t]; sns[t] = norm_scale[t]; }
    if (t < 32) sWc1[t >> 4][t & 15] = Wc1[t];
    if (t == 0) sbc2 = bc2[0];
    __syncthreads();

    // ---- per-batch tiny math (first warp; redundant per block) ----
    const float invN = 1.f / (float)N_;
    if (t < 32) {
        int p = t >> 2;
        int q = t & 3;
        float fim = g_fimraw[b * 8 + p] * invN;
        float feat[10];
#pragma unroll
        for (int c = 0; c < 4; c++) feat[c] = hyp[(b * 8 + p) * 4 + c];
#pragma unroll
        for (int c = 0; c < 4; c++) {
            float v = b_ws[c];
#pragma unroll
            for (int d = 0; d < 16; d++)
                v = fmaf(g_wsumAcc[b * 16 + d] * invN, W_ws[d * 4 + c], v);
            feat[4 + c] = v;
        }
        feat[8] = fim; feat[9] = fim;
        float sp[5] = {0.f, 0.f, 0.f, 0.f, 0.f};
        for (int j = q; j < 64; j += 4) {
            float h = b_s1[j];
#pragma unroll
            for (int i = 0; i < 10; i++) h = fmaf(feat[i], sW1[i * 64 + j], h);
            h = fmaxf(h, 0.f);
#pragma unroll
            for (int c = 0; c < 5; c++) sp[c] = fmaf(h, sW2[j * 5 + c], sp[c]);
        }
#pragma unroll
        for (int c = 0; c < 5; c++) {
            sp[c] += __shfl_xor_sync(0xffffffffu, sp[c], 1);
            sp[c] += __shfl_xor_sync(0xffffffffu, sp[c], 2);
        }
        if (q == 0) {
            s_fim[p] = fim;
#pragma unroll
            for (int c = 0; c < 4; c++) s_nh[p][c] = feat[c] + sp[c] + b_s2[c];
            s_logit[p] = sp[4] + b_s2[4];
        }
        __syncwarp();
        if (t == 0) {
            float mx = -1e30f;
#pragma unroll
            for (int k = 0; k < 8; k++) mx = fmaxf(mx, s_logit[k]);
            float e[8], se = 0.f;
#pragma unroll
            for (int k = 0; k < 8; k++) { e[k] = __expf(s_logit[k] - mx); se += e[k]; }
            float inv = 1.f / se;
            float agg[4] = {0.f, 0.f, 0.f, 0.f};
#pragma unroll
            for (int k = 0; k < 8; k++) {
                float w = e[k] * inv;
                s_w[k] = w;
#pragma unroll
                for (int c = 0; c < 4; c++) agg[c] = fmaf(w, s_nh[k][c], agg[c]);
            }
#pragma unroll
            for (int c = 0; c < 4; c++) s_agg[c] = agg[c];
        }
        __syncwarp();
        if (t < 16) {
            float v = b_lift[t];
#pragma unroll
            for (int c = 0; c < 4; c++) v = fmaf(s_agg[c], W_lift[c * 16 + t], v);
            s_mod[t] = 1.f + tanhf(v);
        }
    }
    __syncthreads();

    // ---- block x==0 writes small outputs + rotor ----
    if (bx == 0) {
        if (t < 8) { out_fim[b * 8 + t] = s_fim[t]; out_w[b * 8 + t] = s_w[t]; }
        if (t < 32) out_newhyp[b * 32 + t] = s_nh[t >> 2][t & 3];
        if (t < 16) {
            float v = 0.f;
#pragma unroll
            for (int k = 0; k < 8; k++) v = fmaf(s_w[k], rotors[k * 16 + t], v);
            s_Rt[t] = v;
            s_Racc[t] = R_accum[b * 16 + t];
        }
    }
    __syncthreads();
    if (bx == 0 && t < 16) {
        float v = 0.f;
#pragma unroll
        for (int a = 0; a < 16; a++) {
            int bb = a ^ t;
            v = fmaf(sC[a * 16 + bb] * s_Rt[a], s_Racc[bb], v);
        }
        s_Rn[t] = v;
    }
    __syncthreads();
    if (bx == 0 && t == 0) {
        float g0 = 0.f;
#pragma unroll
        for (int a = 0; a < 16; a++)
            g0 += sC[a * 16 + a] * s_Rn[a] * s_Rn[a] * rev_sign(a);
        s_g0 = rsqrtf(fmaxf(fabsf(g0), 1e-6f));
    }
    __syncthreads();
    if (bx == 0 && t < 16) out_R[b * 16 + t] = s_Rn[t] * s_g0;

    // ---- per-cell: recompute candidates, weighted sum ----
    float att[16];
    const float4* ap = (const float4*)(g_att + ((size_t)b * N_ + n) * 16);
#pragma unroll
    for (int i = 0; i < 4; i++) { float4 v = ap[i]; att[4*i]=v.x; att[4*i+1]=v.y; att[4*i+2]=v.z; att[4*i+3]=v.w; }
    ull av[16];
#pragma unroll
    for (int d = 0; d < 16; d++) av[d] = pack2(att[d], att[d]);

    float ns_[16];
#pragma unroll
    for (int e = 0; e < 16; e++) ns_[e] = 0.f;
#pragma unroll
    for (int k = 0; k < 8; k++) {
        ull acc[8];
#pragma unroll
        for (int e2 = 0; e2 < 8; e2++) acc[e2] = ((const ull*)&sAb[k][0])[e2];
#pragma unroll
        for (int d = 0; d < 16; d++) {
            const ull* wr = (const ull*)&sWa[k][d][0];
#pragma unroll
            for (int e2 = 0; e2 < 8; e2++) FMA2(acc[e2], av[d], wr[e2], acc[e2]);
        }
        float wk = s_w[k];
#pragma unroll
        for (int e2 = 0; e2 < 8; e2++) {
            float v0, v1; unpack2(acc[e2], v0, v1);
            ns_[2*e2]   = fmaf(wk, fast_tanh(v0), ns_[2*e2]);
            ns_[2*e2+1] = fmaf(wk, fast_tanh(v1), ns_[2*e2+1]);
        }
    }

    float in[32];
    const float4* sp = (const float4*)(state + ((size_t)b * N_ + n) * 16);
#pragma unroll
    for (int i = 0; i < 4; i++) { float4 v = sp[i]; in[4*i]=v.x; in[4*i+1]=v.y; in[4*i+2]=v.z; in[4*i+3]=v.w; }
#pragma unroll
    for (int e = 0; e < 16; e++) { ns_[e] *= s_mod[e]; in[16 + e] = ns_[e]; }

    ull accE[8];
#pragma unroll
    for (int e2 = 0; e2 < 8; e2++) accE[e2] = ((const ull*)sbg2)[e2];
#pragma unroll
    for (int half = 0; half < 2; half++) {
        ull accH[16];
#pragma unroll
        for (int j2 = 0; j2 < 16; j2++) accH[j2] = ((const ull*)sbg1)[half * 16 + j2];
#pragma unroll
        for (int i = 0; i < 32; i++) {
            ull ind = pack2(in[i], in[i]);
            const ull* wrow = (const ull*)&sWg1[i][half * 32];
#pragma unroll
            for (int j2 = 0; j2 < 16; j2++) FMA2(accH[j2], ind, wrow[j2], accH[j2]);
        }
#pragma unroll
        for (int j2 = 0; j2 < 16; j2++) {
            float h0, h1; unpack2(accH[j2], h0, h1);
            h0 = fmaxf(h0, 0.f); h1 = fmaxf(h1, 0.f);
            int j = half * 32 + j2 * 2;
            ull hd0 = pack2(h0, h0), hd1 = pack2(h1, h1);
            const ull* w0 = (const ull*)&sWg2[j][0];
            const ull* w1 = (const ull*)&sWg2[j + 1][0];
#pragma unroll
            for (int e2 = 0; e2 < 8; e2++) {
                FMA2(accE[e2], hd0, w0[e2], accE[e2]);
                FMA2(accE[e2], hd1, w1[e2], accE[e2]);
            }
        }
    }
    float gate[16];
#pragma unroll
    for (int e2 = 0; e2 < 8; e2++) {
        float a0, a1; unpack2(accE[e2], a0, a1);
        gate[2*e2]   = rcpf(1.f + ex2f(-LOG2E_ * a0));
        gate[2*e2+1] = rcpf(1.f + ex2f(-LOG2E_ * a1));
    }

    float cg = sbc2;
#pragma unroll
    for (int j = 0; j < 16; j++) {
        float h = fmaf(in[0], sWc1[0][j], fmaf(ns_[0], sWc1[1][j], sbc1[j]));
        h = fmaxf(h, 0.f);
        cg = fmaf(h, sWc2[j], cg);
    }
    cg = rcpf(1.f + ex2f(-LOG2E_ * cg));

    float val[16];
    val[0] = cg * ns_[0] + (1.f - cg) * in[0];
#pragma unroll
    for (int d = 1; d < 16; d++) val[d] = gate[d] * ns_[d] + (1.f - gate[d]) * in[d];

    float ms = 0.f;
#pragma unroll
    for (int d = 0; d < 16; d++) ms = fmaf(val[d], val[d], ms);
    float r = rsqrtf(ms * (1.f / 16.f) + 1e-6f);

    float4* no = (float4*)(out_ns + ((size_t)b * N_ + n) * 16);
    float4* go = (float4*)(out_gate + ((size_t)b * N_ + n) * 16);
#pragma unroll
    for (int i = 0; i < 4; i++) {
        no[i] = make_float4(val[4*i] * sns[4*i] * r, val[4*i+1] * sns[4*i+1] * r,
                            val[4*i+2] * sns[4*i+2] * r, val[4*i+3] * sns[4*i+3] * r);
        go[i] = make_float4(gate[4*i], gate[4*i+1], gate[4*i+2], gate[4*i+3]);
    }
}

// ---------------- launch ----------------
extern "C" void kernel_launch(void* const* d_in, const int* in_sizes, int n_in,
                              void* d_out, int out_size) {
    const float* state   = (const float*)d_in[0];
    const float* hyp     = (const float*)d_in[1];
    const float* R_accum = (const float*)d_in[2];
    const float* Wq = (const float*)d_in[4];
    const float* bq = (const float*)d_in[5];
    const float* Wk = (const float*)d_in[6];
    const float* bk = (const float*)d_in[7];
    const float* v_gains = (const float*)d_in[8];
    const float* W_act = (const float*)d_in[9];
    const float* b_act = (const float*)d_in[10];
    const float* W_hyp = (const float*)d_in[11];
    const float* b_hyp = (const float*)d_in[12];
    const float* W_ws = (const float*)d_in[13];
    const float* b_ws = (const float*)d_in[14];
    const float* W_s1 = (const float*)d_in[15];
    const float* b_s1 = (const float*)d_in[16];
    const float* W_s2 = (const float*)d_in[17];
    const float* b_s2 = (const float*)d_in[18];
    const float* W_lift = (const float*)d_in[19];
    const float* b_lift = (const float*)d_in[20];
    const float* Wg1 = (const float*)d_in[21];
    const float* bg1 = (const float*)d_in[22];
    const float* Wg2 = (const float*)d_in[23];
    const float* bg2 = (const float*)d_in[24];
    const float* Wc1 = (const float*)d_in[25];
    const float* bc1 = (const float*)d_in[26];
    const float* Wc2 = (const float*)d_in[27];
    const float* bc2 = (const float*)d_in[28];
    const float* norm_scale = (const float*)d_in[29];
    const float* rotors = (const float*)d_in[30];

    float* out = (float*)d_out;
    float* out_ns     = out;
    float* out_newhyp = out + (size_t)B_ * N_ * D_;
    float* out_R      = out_newhyp + B_ * K_ * 4;
    float* out_fim    = out_R + B_ * 16;
    float* out_w      = out_fim + B_ * K_;
    float* out_gate   = out_w + B_ * K_;

    proj_kernel<<<(B_ * N_) / 128, 128>>>(state, Wq, bq, Wk, bk, hyp, W_hyp, b_hyp);
    attn_kernel<<<dim3(N_ / 128, B_), 256>>>(state, v_gains, W_act, b_act);
    final_kernel<<<dim3(N_ / 128, B_), 128>>>(state, hyp, R_accum, W_ws, b_ws,
                                              W_s1, b_s1, W_s2, b_s2, W_lift, b_lift, rotors,
                                              W_act, b_act,
                                              Wg1, bg1, Wg2, bg2, Wc1, bc1, Wc2, bc2, norm_scale,
                                              out_ns, out_newhyp, out_R, out_fim, out_w, out_gate);
}

// round 8
// speedup vs baseline: 1.0236x; 1.0236x over previous
#include <cuda_runtime.h>
#include <math.h>

// ---------------- problem constants ----------------
#define B_  8
#define N_  2048
#define D_  16
#define K_  8
#define SCALE_ 0.35355339059327373f     // hd^-0.5
#define LOG2E_ 1.4426950408889634f

typedef unsigned long long ull;

// ---------------- packed f32x2 helpers ----------------
#define FMA2(d, a, b, c) asm("fma.rn.f32x2 %0, %1, %2, %3;" : "=l"(d) : "l"(a), "l"(b), "l"(c))
#define ADD2(d, a, b)    asm("add.rn.f32x2 %0, %1, %2;"     : "=l"(d) : "l"(a), "l"(b))
__device__ __forceinline__ ull pack2(float lo, float hi) {
    ull r; asm("mov.b64 %0, {%1, %2};" : "=l"(r) : "f"(lo), "f"(hi)); return r;
}
__device__ __forceinline__ void unpack2(ull v, float& lo, float& hi) {
    asm("mov.b64 {%0, %1}, %2;" : "=f"(lo), "=f"(hi) : "l"(v));
}
__device__ __forceinline__ float ex2f(float x) {
    float r; asm("ex2.approx.f32 %0, %1;" : "=f"(r) : "f"(x)); return r;
}
__device__ __forceinline__ float rcpf(float x) {
    float r; asm("rcp.approx.f32 %0, %1;" : "=f"(r) : "f"(x)); return r;
}
__device__ __forceinline__ float fast_tanh(float x) {
    float e = ex2f(2.8853900817779268f * x);
    return fmaf(-2.f, rcpf(e + 1.f), 1.f);
}

// ---------------- scratch ----------------
__device__ float g_Q   [B_ * N_ * 32];
__device__ float g_Kt  [B_ * N_ * 32];
__device__ float g_att [B_ * N_ * D_];
__device__ float g_cand[(size_t)B_ * K_ * N_ * D_];
__device__ float g_wsumAcc[B_ * D_];
__device__ float g_hypf[B_ * K_ * D_];
__device__ float g_fimraw[B_ * K_];

// ---------------- Cl(3,0,1) helpers ----------------
__device__ __forceinline__ float cayley_sign(int a, int b) {
    int neg = 0;
#pragma unroll
    for (int i = 0; i < 4; i++)
        if ((b >> i) & 1) neg ^= (__popc(a >> (i + 1)) & 1);
    if ((a & b) & 8) return 0.f;
    return neg ? -1.f : 1.f;
}
__device__ __forceinline__ float rev_sign(int i) {
    int p = __popc(i);
    return ((p * (p - 1) / 2) & 1) ? -1.f : 1.f;
}

// ---------------- kernel 1: Q/K projection (+ init) ----------------
__global__ __launch_bounds__(128) void proj_kernel(const float* __restrict__ state,
                            const float* __restrict__ Wq, const float* __restrict__ bq,
                            const float* __restrict__ Wk, const float* __restrict__ bk,
                            const float* __restrict__ hyp,
                            const float* __restrict__ W_hyp,
                            const float* __restrict__ b_hyp) {
    __shared__ __align__(16) float sWq[16][32], sWk[16][32], sbq[32], sbk[32];
    int t = threadIdx.x;
    if (blockIdx.x == 0) {
        if (t < B_ * K_) g_fimraw[t] = 0.f;
        if (t < B_ * D_) g_wsumAcc[t] = 0.f;
        for (int i = t; i < B_ * K_ * D_; i += 128) {
            int bk_ = i >> 4, d = i & 15;
            float v = b_hyp[d];
#pragma unroll
            for (int c = 0; c < 4; c++) v = fmaf(hyp[bk_ * 4 + c], W_hyp[c * D_ + d], v);
            g_hypf[i] = v;
        }
    }
    for (int i = t; i < 512; i += 128) { sWq[i >> 5][i & 31] = Wq[i]; sWk[i >> 5][i & 31] = Wk[i]; }
    if (t < 32) { sbq[t] = bq[t]; sbk[t] = bk[t]; }
    __syncthreads();
    size_t row = (size_t)blockIdx.x * 128 + t;
    float s[16];
    const float4* sp = (const float4*)(state + row * 16);
#pragma unroll
    for (int i = 0; i < 4; i++) { float4 v = sp[i]; s[4*i]=v.x; s[4*i+1]=v.y; s[4*i+2]=v.z; s[4*i+3]=v.w; }
    ull sd[16];
#pragma unroll
    for (int d = 0; d < 16; d++) sd[d] = pack2(s[d], s[d]);
    ull* qo = (ull*)(g_Q  + row * 32);
    ull* ko = (ull*)(g_Kt + row * 32);
#pragma unroll
    for (int c2 = 0; c2 < 16; c2++) {
        ull aq = ((const ull*)sbq)[c2];
        ull ak = ((const ull*)sbk)[c2];
#pragma unroll
        for (int d = 0; d < 16; d++) {
            FMA2(aq, sd[d], ((const ull*)&sWq[d][0])[c2], aq);
            FMA2(ak, sd[d], ((const ull*)&sWk[d][0])[c2], ak);
        }
        qo[c2] = aq; ko[c2] = ak;
    }
}

// ---------------- kernel 2: fused attention (128 rows/block, 256 thr) ----------------
#define TM_ 128
__global__ __launch_bounds__(256, 1) void attn_kernel(const float* __restrict__ state,
                                                      const float* __restrict__ v_gains) {
    int b    = blockIdx.y;
    int t    = threadIdx.x;
    int head = t & 3;
    int g    = t >> 2;                         // 0..63
    int n0   = blockIdx.x * 128 + g * 2;

    __shared__ __align__(16) float Ks[TM_][32];
    __shared__ __align__(16) float Ss[TM_][16];
    __shared__ float sW[8][16];

    // q prescaled into log2 domain
    const float qs = SCALE_ * LOG2E_;
    ull q[2][4];
#pragma unroll
    for (int r = 0; r < 2; r++) {
        const float4* qp = (const float4*)(g_Q + ((size_t)b * N_ + n0 + r) * 32 + head * 8);
        float4 a = qp[0], c = qp[1];
        q[r][0] = pack2(a.x * qs, a.y * qs);
        q[r][1] = pack2(a.z * qs, a.w * qs);
        q[r][2] = pack2(c.x * qs, c.y * qs);
        q[r][3] = pack2(c.z * qs, c.w * qs);
    }
    ull o[2][8];
#pragma unroll
    for (int r = 0; r < 2; r++)
#pragma unroll
        for (int j = 0; j < 8; j++) o[r][j] = 0ULL;
    ull lacc = 0ULL;                           // packed (l0, l1)

    for (int m0 = 0; m0 < N_; m0 += TM_) {
        __syncthreads();
#pragma unroll
        for (int i = 0; i < 4; i++) {
            int idx = t + i * 256;             // Ks: 1024 float4
            int r = idx >> 3, c = idx & 7;
            ((float4*)&Ks[r][0])[c] = ((const float4*)(g_Kt + ((size_t)b * N_ + m0 + r) * 32))[c];
        }
#pragma unroll
        for (int i = 0; i < 2; i++) {
            int idx = t + i * 256;             // Ss: 512 float4
            int r = idx >> 2, c = idx & 3;
            ((float4*)&Ss[r][0])[c] = ((const float4*)(state + ((size_t)b * N_ + m0 + r) * 16))[c];
        }
        __syncthreads();
#pragma unroll 4
        for (int mm = 0; mm < TM_; mm++) {
            const ulonglong2* kp = (const ulonglong2*)&Ks[mm][head * 8];
            ulonglong2 ka = kp[0], kb = kp[1];
            const ulonglong2* vp = (const ulonglong2*)&Ss[mm][0];
            ulonglong2 va = vp[0], vb = vp[1], vc = vp[2], vd = vp[3];
            ull acc0, acc1;
            FMA2(acc0, q[0][0], ka.x, 0ULL);
            FMA2(acc0, q[0][1], ka.y, acc0);
            FMA2(acc0, q[0][2], kb.x, acc0);
            FMA2(acc0, q[0][3], kb.y, acc0);
            FMA2(acc1, q[1][0], ka.x, 0ULL);
            FMA2(acc1, q[1][1], ka.y, acc1);
            FMA2(acc1, q[1][2], kb.x, acc1);
            FMA2(acc1, q[1][3], kb.y, acc1);
            float lo0, hi0, lo1, hi1;
            unpack2(acc0, lo0, hi0);
            unpack2(acc1, lo1, hi1);
            ull ssum;                           // (lo0+hi0, lo1+hi1) in one ADD2
            ADD2(ssum, pack2(lo0, lo1), pack2(hi0, hi1));
            float s0, s1; unpack2(ssum, s0, s1);
            float p0 = ex2f(s0), p1 = ex2f(s1);
            ADD2(lacc, lacc, pack2(p0, p1));    // both rows' l in one ADD2
            ull pp0 = pack2(p0, p0), pp1 = pack2(p1, p1);
            FMA2(o[0][0], pp0, va.x, o[0][0]);
            FMA2(o[0][1], pp0, va.y, o[0][1]);
            FMA2(o[0][2], pp0, vb.x, o[0][2]);
            FMA2(o[0][3], pp0, vb.y, o[0][3]);
            FMA2(o[0][4], pp0, vc.x, o[0][4]);
            FMA2(o[0][5], pp0, vc.y, o[0][5]);
            FMA2(o[0][6], pp0, vd.x, o[0][6]);
            FMA2(o[0][7], pp0, vd.y, o[0][7]);
            FMA2(o[1][0], pp1, va.x, o[1][0]);
            FMA2(o[1][1], pp1, va.y, o[1][1]);
            FMA2(o[1][2], pp1, vb.x, o[1][2]);
            FMA2(o[1][3], pp1, vb.y, o[1][3]);
            FMA2(o[1][4], pp1, vc.x, o[1][4]);
            FMA2(o[1][5], pp1, vc.y, o[1][5]);
            FMA2(o[1][6], pp1, vd.x, o[1][6]);
            FMA2(o[1][7], pp1, vd.y, o[1][7]);
        }
    }

    // epilogue: head combine + write + world-summary partials
    float l0, l1; unpack2(lacc, l0, l1);
    float gain = 0.25f * v_gains[0];
    float wacc[16];
#pragma unroll
    for (int d = 0; d < 16; d++) wacc[d] = 0.f;
#pragma unroll
    for (int r = 0; r < 2; r++) {
        float inv = rcpf(r == 0 ? l0 : l1);
        float ov[16];
#pragma unroll
        for (int j = 0; j < 8; j++) unpack2(o[r][j], ov[2*j], ov[2*j+1]);
#pragma unroll
        for (int d = 0; d < 16; d++) {
            float v = ov[d] * inv;
            v += __shfl_xor_sync(0xffffffffu, v, 1);
            v += __shfl_xor_sync(0xffffffffu, v, 2);
            v *= gain;
            ov[d] = v;
            wacc[d] += v;
        }
        if (head == 0) {
            float4* ap = (float4*)(g_att + ((size_t)b * N_ + n0 + r) * 16);
#pragma unroll
            for (int i = 0; i < 4; i++)
                ap[i] = make_float4(ov[4*i], ov[4*i+1], ov[4*i+2], ov[4*i+3]);
        }
    }
#pragma unroll
    for (int d = 0; d < 16; d++) {
        float v = wacc[d];
        v += __shfl_xor_sync(0xffffffffu, v, 4);
        v += __shfl_xor_sync(0xffffffffu, v, 8);
        v += __shfl_xor_sync(0xffffffffu, v, 16);
        wacc[d] = v;
    }
    if ((t & 31) == 0) {
#pragma unroll
        for (int d = 0; d < 16; d++) sW[t >> 5][d] = wacc[d];
    }
    __syncthreads();
    if (t < 16) {
        float s = 0.f;
#pragma unroll
        for (int w = 0; w < 8; w++) s += sW[w][t];
        atomicAdd(&g_wsumAcc[b * 16 + t], s);
    }
}

// ---------------- kernel 3: candidates + fim partials ----------------
__global__ __launch_bounds__(256) void cand_kernel(const float* __restrict__ W_act,
                            const float* __restrict__ b_act) {
    int b = blockIdx.z, k = blockIdx.y, ch = blockIdx.x;
    __shared__ __align__(16) float W[16][16];
    __shared__ __align__(16) float bias[16];
    int t = threadIdx.x;
    W[t >> 4][t & 15] = W_act[(k * 16 + (t >> 4)) * 16 + (t & 15)];
    if (t < 16) bias[t] = b_act[k * 16 + t] + g_hypf[(b * K_ + k) * 16 + t];
    __syncthreads();
    int n = ch * 256 + t;
    float a[16];
    const float4* ap = (const float4*)(g_att + ((size_t)b * N_ + n) * 16);
#pragma unroll
    for (int i = 0; i < 4; i++) { float4 v = ap[i]; a[4*i]=v.x; a[4*i+1]=v.y; a[4*i+2]=v.z; a[4*i+3]=v.w; }
    ull ad[16];
#pragma unroll
    for (int d = 0; d < 16; d++) ad[d] = pack2(a[d], a[d]);
    float c[16], ss = 0.f;
#pragma unroll
    for (int e2 = 0; e2 < 8; e2++) {
        ull acc = ((const ull*)bias)[e2];
#pragma unroll
        for (int d = 0; d < 16; d++) FMA2(acc, ad[d], ((const ull*)&W[d][0])[e2], acc);
        float v0, v1; unpack2(acc, v0, v1);
        v0 = fast_tanh(v0); v1 = fast_tanh(v1);
        c[2*e2] = v0; c[2*e2+1] = v1;
        ss = fmaf(v0, v0, fmaf(v1, v1, ss));
    }
    float4* cp = (float4*)(g_cand + (((size_t)(b * K_ + k)) * N_ + n) * 16);
#pragma unroll
    for (int i = 0; i < 4; i++) cp[i] = make_float4(c[4*i], c[4*i+1], c[4*i+2], c[4*i+3]);
    ss *= (1.f / 16.f);
#pragma unroll
    for (int off = 16; off > 0; off >>= 1) ss += __shfl_xor_sync(0xffffffffu, ss, off);
    __shared__ float wsums[8];
    if ((t & 31) == 0) wsums[t >> 5] = ss;
    __syncthreads();
    if (t == 0) {
        float tot = 0.f;
#pragma unroll
        for (int i = 0; i < 8; i++) tot += wsums[i];
        atomicAdd(&g_fimraw[b * K_ + k], tot);
    }
}

// ---------------- kernel 4: fused small-math + weighted select + gates + norm ----------------
__global__ __launch_bounds__(128) void final_kernel(const float* __restrict__ state,
                            const float* __restrict__ hyp, const float* __restrict__ R_accum,
                            const float* __restrict__ W_ws, const float* __restrict__ b_ws,
                            const float* __restrict__ W_s1, const float* __restrict__ b_s1,
                            const float* __restrict__ W_s2, const float* __restrict__ b_s2,
                            const float* __restrict__ W_lift, const float* __restrict__ b_lift,
                            const float* __restrict__ rotors,
                            const float* __restrict__ Wg1, const float* __restrict__ bg1,
                            const float* __restrict__ Wg2, const float* __restrict__ bg2,
                            const float* __restrict__ Wc1, const float* __restrict__ bc1,
                            const float* __restrict__ Wc2, const float* __restrict__ bc2,
                            const float* __restrict__ norm_scale,
                            float* __restrict__ out_ns, float* __restrict__ out_newhyp,
                            float* __restrict__ out_R, float* __restrict__ out_fim,
                            float* __restrict__ out_w, float* __restrict__ out_gate) {
    int b = blockIdx.y;
    int bx = blockIdx.x;
    int t = threadIdx.x;
    int n = bx * 128 + t;

    __shared__ __align__(16) float sWg1[32][64];
    __shared__ __align__(16) float sWg2[64][16];
    __shared__ __align__(16) float sbg1[64], sbg2[16];
    __shared__ float sWc1[2][16], sbc1[16], sWc2[16], sns[16];
    __shared__ float sW1[640], sW2[320];
    __shared__ float sC[256];
    __shared__ float s_nh[8][4], s_logit[8], s_fim[8];
    __shared__ float s_w[8], s_agg[4], s_mod[16];
    __shared__ float s_Rt[16], s_Racc[16], s_Rn[16];
    __shared__ float sbc2, s_g0;

    // ---- stage weights ----
    for (int i = t; i < 2048; i += 128) sWg1[i >> 6][i & 63] = Wg1[i];
    for (int i = t; i < 1024; i += 128) sWg2[i >> 4][i & 15] = Wg2[i];
    for (int i = t; i < 640; i += 128) sW1[i] = W_s1[i];
    for (int i = t; i < 320; i += 128) sW2[i] = W_s2[i];
    for (int i = t; i < 256; i += 128) sC[i] = cayley_sign(i >> 4, i & 15);
    if (t < 64) sbg1[t] = bg1[t];
    if (t < 16) { sbg2[t] = bg2[t]; sbc1[t] = bc1[t]; sWc2[t] = Wc2[t]; sns[t] = norm_scale[t]; }
    if (t < 32) sWc1[t >> 4][t & 15] = Wc1[t];
    if (t == 0) sbc2 = bc2[0];
    __syncthreads();

    // ---- per-batch tiny math (first warp; redundant per block) ----
    const float invN = 1.f / (float)N_;
    if (t < 32) {
        int p = t >> 2;
        int q = t & 3;
        float fim = g_fimraw[b * 8 + p] * invN;
        float feat[10];
#pragma unroll
        for (int c = 0; c < 4; c++) feat[c] = hyp[(b * 8 + p) * 4 + c];
#pragma unroll
        for (int c = 0; c < 4; c++) {
            float v = b_ws[c];
#pragma unroll
            for (int d = 0; d < 16; d++)
                v = fmaf(g_wsumAcc[b * 16 + d] * invN, W_ws[d * 4 + c], v);
            feat[4 + c] = v;
        }
        feat[8] = fim; feat[9] = fim;
        float sp[5] = {0.f, 0.f, 0.f, 0.f, 0.f};
        for (int j = q; j < 64; j += 4) {
            float h = b_s1[j];
#pragma unroll
            for (int i = 0; i < 10; i++) h = fmaf(feat[i], sW1[i * 64 + j], h);
            h = fmaxf(h, 0.f);
#pragma unroll
            for (int c = 0; c < 5; c++) sp[c] = fmaf(h, sW2[j * 5 + c], sp[c]);
        }
#pragma unroll
        for (int c = 0; c < 5; c++) {
            sp[c] += __shfl_xor_sync(0xffffffffu, sp[c], 1);
            sp[c] += __shfl_xor_sync(0xffffffffu, sp[c], 2);
        }
        if (q == 0) {
            s_fim[p] = fim;
#pragma unroll
            for (int c = 0; c < 4; c++) s_nh[p][c] = feat[c] + sp[c] + b_s2[c];
            s_logit[p] = sp[4] + b_s2[4];
        }
        __syncwarp();
        if (t == 0) {
            float mx = -1e30f;
#pragma unroll
            for (int k = 0; k < 8; k++) mx = fmaxf(mx, s_logit[k]);
            float e[8], se = 0.f;
#pragma unroll
            for (int k = 0; k < 8; k++) { e[k] = __expf(s_logit[k] - mx); se += e[k]; }
            float inv = 1.f / se;
            float agg[4] = {0.f, 0.f, 0.f, 0.f};
#pragma unroll
            for (int k = 0; k < 8; k++) {
                float w = e[k] * inv;
                s_w[k] = w;
#pragma unroll
                for (int c = 0; c < 4; c++) agg[c] = fmaf(w, s_nh[k][c], agg[c]);
            }
#pragma unroll
            for (int c = 0; c < 4; c++) s_agg[c] = agg[c];
        }
        __syncwarp();
        if (t < 16) {
            float v = b_lift[t];
#pragma unroll
            for (int c = 0; c < 4; c++) v = fmaf(s_agg[c], W_lift[c * 16 + t], v);
            s_mod[t] = 1.f + tanhf(v);
        }
    }
    __syncthreads();

    // ---- block x==0 writes small outputs + rotor ----
    if (bx == 0) {
        if (t < 8) { out_fim[b * 8 + t] = s_fim[t]; out_w[b * 8 + t] = s_w[t]; }
        if (t < 32) out_newhyp[b * 32 + t] = s_nh[t >> 2][t & 3];
        if (t < 16) {
            float v = 0.f;
#pragma unroll
            for (int k = 0; k < 8; k++) v = fmaf(s_w[k], rotors[k * 16 + t], v);
            s_Rt[t] = v;
            s_Racc[t] = R_accum[b * 16 + t];
        }
    }
    __syncthreads();
    if (bx == 0 && t < 16) {
        float v = 0.f;
#pragma unroll
        for (int a = 0; a < 16; a++) {
            int bb = a ^ t;
            v = fmaf(sC[a * 16 + bb] * s_Rt[a], s_Racc[bb], v);
        }
        s_Rn[t] = v;
    }
    __syncthreads();
    if (bx == 0 && t == 0) {
        float g0 = 0.f;
#pragma unroll
        for (int a = 0; a < 16; a++)
            g0 += sC[a * 16 + a] * s_Rn[a] * s_Rn[a] * rev_sign(a);
        s_g0 = rsqrtf(fmaxf(fabsf(g0), 1e-6f));
    }
    __syncthreads();
    if (bx == 0 && t < 16) out_R[b * 16 + t] = s_Rn[t] * s_g0;

    // ---- per-cell main work ----
    float in[32];
    const float4* sp = (const float4*)(state + ((size_t)b * N_ + n) * 16);
#pragma unroll
    for (int i = 0; i < 4; i++) { float4 v = sp[i]; in[4*i]=v.x; in[4*i+1]=v.y; in[4*i+2]=v.z; in[4*i+3]=v.w; }

    float ns_[16];
#pragma unroll
    for (int e = 0; e < 16; e++) ns_[e] = 0.f;
#pragma unroll
    for (int k = 0; k < 8; k++) {
        const float4* cp = (const float4*)(g_cand + (((size_t)(b * K_ + k)) * N_ + n) * 16);
        float wk = s_w[k];
#pragma unroll
        for (int i = 0; i < 4; i++) {
            float4 v = cp[i];
            ns_[4*i]   = fmaf(wk, v.x, ns_[4*i]);
            ns_[4*i+1] = fmaf(wk, v.y, ns_[4*i+1]);
            ns_[4*i+2] = fmaf(wk, v.z, ns_[4*i+2]);
            ns_[4*i+3] = fmaf(wk, v.w, ns_[4*i+3]);
        }
    }
#pragma unroll
    for (int e = 0; e < 16; e++) { ns_[e] *= s_mod[e]; in[16 + e] = ns_[e]; }

    ull accE[8];
#pragma unroll
    for (int e2 = 0; e2 < 8; e2++) accE[e2] = ((const ull*)sbg2)[e2];
#pragma unroll
    for (int half = 0; half < 2; half++) {
        ull accH[16];
#pragma unroll
        for (int j2 = 0; j2 < 16; j2++) accH[j2] = ((const ull*)sbg1)[half * 16 + j2];
#pragma unroll
        for (int i = 0; i < 32; i++) {
            ull ind = pack2(in[i], in[i]);
            const ull* wrow = (const ull*)&sWg1[i][half * 32];
#pragma unroll
            for (int j2 = 0; j2 < 16; j2++) FMA2(accH[j2], ind, wrow[j2], accH[j2]);
        }
#pragma unroll
        for (int j2 = 0; j2 < 16; j2++) {
            float h0, h1; unpack2(accH[j2], h0, h1);
            h0 = fmaxf(h0, 0.f); h1 = fmaxf(h1, 0.f);
            int j = half * 32 + j2 * 2;
            ull hd0 = pack2(h0, h0), hd1 = pack2(h1, h1);
            const ull* w0 = (const ull*)&sWg2[j][0];
            const ull* w1 = (const ull*)&sWg2[j + 1][0];
#pragma unroll
            for (int e2 = 0; e2 < 8; e2++) {
                FMA2(accE[e2], hd0, w0[e2], accE[e2]);
                FMA2(accE[e2], hd1, w1[e2], accE[e2]);
            }
        }
    }
    float gate[16];
#pragma unroll
    for (int e2 = 0; e2 < 8; e2++) {
        float a0, a1; unpack2(accE[e2], a0, a1);
        gate[2*e2]   = rcpf(1.f + ex2f(-LOG2E_ * a0));
        gate[2*e2+1] = rcpf(1.f + ex2f(-LOG2E_ * a1));
    }

    float cg = sbc2;
#pragma unroll
    for (int j = 0; j < 16; j++) {
        float h = fmaf(in[0], sWc1[0][j], fmaf(ns_[0], sWc1[1][j], sbc1[j]));
        h = fmaxf(h, 0.f);
        cg = fmaf(h, sWc2[j], cg);
    }
    cg = rcpf(1.f + ex2f(-LOG2E_ * cg));

    float val[16];
    val[0] = cg * ns_[0] + (1.f - cg) * in[0];
#pragma unroll
    for (int d = 1; d < 16; d++) val[d] = gate[d] * ns_[d] + (1.f - gate[d]) * in[d];

    float ms = 0.f;
#pragma unroll
    for (int d = 0; d < 16; d++) ms = fmaf(val[d], val[d], ms);
    float r = rsqrtf(ms * (1.f / 16.f) + 1e-6f);

    float4* no = (float4*)(out_ns + ((size_t)b * N_ + n) * 16);
    float4* go = (float4*)(out_gate + ((size_t)b * N_ + n) * 16);
#pragma unroll
    for (int i = 0; i < 4; i++) {
        no[i] = make_float4(val[4*i] * sns[4*i] * r, val[4*i+1] * sns[4*i+1] * r,
                            val[4*i+2] * sns[4*i+2] * r, val[4*i+3] * sns[4*i+3] * r);
        go[i] = make_float4(gate[4*i], gate[4*i+1], gate[4*i+2], gate[4*i+3]);
    }
}

// ---------------- launch ----------------
extern "C" void kernel_launch(void* const* d_in, const int* in_sizes, int n_in,
                              void* d_out, int out_size) {
    const float* state   = (const float*)d_in[0];
    const float* hyp     = (const float*)d_in[1];
    const float* R_accum = (const float*)d_in[2];
    const float* Wq = (const float*)d_in[4];
    const float* bq = (const float*)d_in[5];
    const float* Wk = (const float*)d_in[6];
    const float* bk = (const float*)d_in[7];
    const float* v_gains = (const float*)d_in[8];
    const float* W_act = (const float*)d_in[9];
    const float* b_act = (const float*)d_in[10];
    const float* W_hyp = (const float*)d_in[11];
    const float* b_hyp = (const float*)d_in[12];
    const float* W_ws = (const float*)d_in[13];
    const float* b_ws = (const float*)d_in[14];
    const float* W_s1 = (const float*)d_in[15];
    const float* b_s1 = (const float*)d_in[16];
    const float* W_s2 = (const float*)d_in[17];
    const float* b_s2 = (const float*)d_in[18];
    const float* W_lift = (const float*)d_in[19];
    const float* b_lift = (const float*)d_in[20];
    const float* Wg1 = (const float*)d_in[21];
    const float* bg1 = (const float*)d_in[22];
    const float* Wg2 = (const float*)d_in[23];
    const float* bg2 = (const float*)d_in[24];
    const float* Wc1 = (const float*)d_in[25];
    const float* bc1 = (const float*)d_in[26];
    const float* Wc2 = (const float*)d_in[27];
    const float* bc2 = (const float*)d_in[28];
    const float* norm_scale = (const float*)d_in[29];
    const float* rotors = (const float*)d_in[30];

    float* out = (float*)d_out;
    float* out_ns     = out;
    float* out_newhyp = out + (size_t)B_ * N_ * D_;
    float* out_R      = out_newhyp + B_ * K_ * 4;
    float* out_fim    = out_R + B_ * 16;
    float* out_w      = out_fim + B_ * K_;
    float* out_gate   = out_w + B_ * K_;

    proj_kernel<<<(B_ * N_) / 128, 128>>>(state, Wq, bq, Wk, bk, hyp, W_hyp, b_hyp);
    attn_kernel<<<dim3(N_ / 128, B_), 256>>>(state, v_gains);
    cand_kernel<<<dim3(N_ / 256, K_, B_), 256>>>(W_act, b_act);
    final_kernel<<<dim3(N_ / 128, B_), 128>>>(state, hyp, R_accum, W_ws, b_ws,
                                              W_s1, b_s1, W_s2, b_s2, W_lift, b_lift, rotors,
                                              Wg1, bg1, Wg2, bg2, Wc1, bc1, Wc2, bc2, norm_scale,
                                              out_ns, out_newhyp, out_R, out_fim, out_w, out_gate);
}

// round 9
// speedup vs baseline: 1.0674x; 1.0428x over previous
#include <cuda_runtime.h>
#include <math.h>

// ---------------- problem constants ----------------
#define B_  8
#define N_  2048
#define D_  16
#define K_  8
#define SCALE_ 0.35355339059327373f     // hd^-0.5
#define LOG2E_ 1.4426950408889634f
#define MSPLIT_ 8

typedef unsigned long long ull;

// ---------------- packed f32x2 helpers ----------------
#define FMA2(d, a, b, c) asm("fma.rn.f32x2 %0, %1, %2, %3;" : "=l"(d) : "l"(a), "l"(b), "l"(c))
#define ADD2(d, a, b)    asm("add.rn.f32x2 %0, %1, %2;"     : "=l"(d) : "l"(a), "l"(b))
__device__ __forceinline__ ull pack2(float lo, float hi) {
    ull r; asm("mov.b64 %0, {%1, %2};" : "=l"(r) : "f"(lo), "f"(hi)); return r;
}
__device__ __forceinline__ void unpack2(ull v, float& lo, float& hi) {
    asm("mov.b64 {%0, %1}, %2;" : "=f"(lo), "=f"(hi) : "l"(v));
}
__device__ __forceinline__ float ex2f(float x) {
    float r; asm("ex2.approx.f32 %0, %1;" : "=f"(r) : "f"(x)); return r;
}
__device__ __forceinline__ float rcpf(float x) {
    float r; asm("rcp.approx.f32 %0, %1;" : "=f"(r) : "f"(x)); return r;
}
__device__ __forceinline__ float fast_tanh(float x) {
    float e = ex2f(2.8853900817779268f * x);
    return fmaf(-2.f, rcpf(e + 1.f), 1.f);
}

// ---------------- scratch ----------------
__device__ float g_Q   [B_ * N_ * 32];
__device__ float g_Kt  [B_ * N_ * 32];
__device__ float g_att [B_ * N_ * D_];
__device__ float g_cand[(size_t)B_ * K_ * N_ * D_];
__device__ float g_oAcc[(size_t)B_ * N_ * 4 * 16];   // unnormalized per-head PV accum
__device__ float g_lAcc[B_ * N_ * 4];                // per-head softmax denominators
__device__ float g_wsumAcc[B_ * D_];
__device__ float g_hypf[B_ * K_ * D_];
__device__ float g_fimraw[B_ * K_];

// ---------------- Cl(3,0,1) helpers ----------------
__device__ __forceinline__ float cayley_sign(int a, int b) {
    int neg = 0;
#pragma unroll
    for (int i = 0; i < 4; i++)
        if ((b >> i) & 1) neg ^= (__popc(a >> (i + 1)) & 1);
    if ((a & b) & 8) return 0.f;
    return neg ? -1.f : 1.f;
}
__device__ __forceinline__ float rev_sign(int i) {
    int p = __popc(i);
    return ((p * (p - 1) / 2) & 1) ? -1.f : 1.f;
}

// ---------------- kernel 1: Q/K projection (+ init/zeroing) ----------------
__global__ __launch_bounds__(128) void proj_kernel(const float* __restrict__ state,
                            const float* __restrict__ Wq, const float* __restrict__ bq,
                            const float* __restrict__ Wk, const float* __restrict__ bk,
                            const float* __restrict__ hyp,
                            const float* __restrict__ W_hyp,
                            const float* __restrict__ b_hyp) {
    __shared__ __align__(16) float sWq[16][32], sWk[16][32], sbq[32], sbk[32];
    int t = threadIdx.x;
    int gid = blockIdx.x * 128 + t;
    {
        float4 z = make_float4(0.f, 0.f, 0.f, 0.f);
        float4* oz = (float4*)g_oAcc;            // 262144 float4
#pragma unroll
        for (int i = 0; i < 16; i++) oz[gid + i * 16384] = z;
        ((float4*)g_lAcc)[gid] = z;              // 16384 float4
    }
    if (blockIdx.x == 0) {
        if (t < B_ * K_) g_fimraw[t] = 0.f;
        if (t < B_ * D_) g_wsumAcc[t] = 0.f;
        for (int i = t; i < B_ * K_ * D_; i += 128) {
            int bk_ = i >> 4, d = i & 15;
            float v = b_hyp[d];
#pragma unroll
            for (int c = 0; c < 4; c++) v = fmaf(hyp[bk_ * 4 + c], W_hyp[c * D_ + d], v);
            g_hypf[i] = v;
        }
    }
    for (int i = t; i < 512; i += 128) { sWq[i >> 5][i & 31] = Wq[i]; sWk[i >> 5][i & 31] = Wk[i]; }
    if (t < 32) { sbq[t] = bq[t]; sbk[t] = bk[t]; }
    __syncthreads();
    size_t row = (size_t)gid;
    float s[16];
    const float4* sp = (const float4*)(state + row * 16);
#pragma unroll
    for (int i = 0; i < 4; i++) { float4 v = sp[i]; s[4*i]=v.x; s[4*i+1]=v.y; s[4*i+2]=v.z; s[4*i+3]=v.w; }
    ull sd[16];
#pragma unroll
    for (int d = 0; d < 16; d++) sd[d] = pack2(s[d], s[d]);
    ull* qo = (ull*)(g_Q  + row * 32);
    ull* ko = (ull*)(g_Kt + row * 32);
#pragma unroll
    for (int c2 = 0; c2 < 16; c2++) {
        ull aq = ((const ull*)sbq)[c2];
        ull ak = ((const ull*)sbk)[c2];
#pragma unroll
        for (int d = 0; d < 16; d++) {
            FMA2(aq, sd[d], ((const ull*)&sWq[d][0])[c2], aq);
            FMA2(ak, sd[d], ((const ull*)&sWk[d][0])[c2], ak);
        }
        qo[c2] = aq; ko[c2] = ak;
    }
}

// ---------------- kernel 2: attention mainloop, m-split 8 ----------------
#define TM_ 128
__global__ __launch_bounds__(256, 1) void attn_kernel(const float* __restrict__ state) {
    int b    = blockIdx.y;
    int t    = threadIdx.x;
    int head = t & 3;
    int g    = t >> 2;                         // 0..63
    int n0   = blockIdx.x * 128 + g * 2;
    int mbase = blockIdx.z * (N_ / MSPLIT_);   // 256 m per block

    __shared__ __align__(16) float Ks[TM_][32];
    __shared__ __align__(16) float Ss[TM_][16];

    const float qs = SCALE_ * LOG2E_;
    ull q[2][4];
#pragma unroll
    for (int r = 0; r < 2; r++) {
        const float4* qp = (const float4*)(g_Q + ((size_t)b * N_ + n0 + r) * 32 + head * 8);
        float4 a = qp[0], c = qp[1];
        q[r][0] = pack2(a.x * qs, a.y * qs);
        q[r][1] = pack2(a.z * qs, a.w * qs);
        q[r][2] = pack2(c.x * qs, c.y * qs);
        q[r][3] = pack2(c.z * qs, c.w * qs);
    }
    ull o[2][8];
#pragma unroll
    for (int r = 0; r < 2; r++)
#pragma unroll
        for (int j = 0; j < 8; j++) o[r][j] = 0ULL;
    ull lacc = 0ULL;

#pragma unroll
    for (int mt = 0; mt < 2; mt++) {
        int m0 = mbase + mt * TM_;
        __syncthreads();
#pragma unroll
        for (int i = 0; i < 4; i++) {
            int idx = t + i * 256;             // Ks: 1024 float4
            int r = idx >> 3, c = idx & 7;
            ((float4*)&Ks[r][0])[c] = ((const float4*)(g_Kt + ((size_t)b * N_ + m0 + r) * 32))[c];
        }
#pragma unroll
        for (int i = 0; i < 2; i++) {
            int idx = t + i * 256;             // Ss: 512 float4
            int r = idx >> 2, c = idx & 3;
            ((float4*)&Ss[r][0])[c] = ((const float4*)(state + ((size_t)b * N_ + m0 + r) * 16))[c];
        }
        __syncthreads();
#pragma unroll 4
        for (int mm = 0; mm < TM_; mm++) {
            const ulonglong2* kp = (const ulonglong2*)&Ks[mm][head * 8];
            ulonglong2 ka = kp[0], kb = kp[1];
            const ulonglong2* vp = (const ulonglong2*)&Ss[mm][0];
            ulonglong2 va = vp[0], vb = vp[1], vc = vp[2], vd = vp[3];
            ull acc0, acc1;
            FMA2(acc0, q[0][0], ka.x, 0ULL);
            FMA2(acc0, q[0][1], ka.y, acc0);
            FMA2(acc0, q[0][2], kb.x, acc0);
            FMA2(acc0, q[0][3], kb.y, acc0);
            FMA2(acc1, q[1][0], ka.x, 0ULL);
            FMA2(acc1, q[1][1], ka.y, acc1);
            FMA2(acc1, q[1][2], kb.x, acc1);
            FMA2(acc1, q[1][3], kb.y, acc1);
            float lo0, hi0, lo1, hi1;
            unpack2(acc0, lo0, hi0);
            unpack2(acc1, lo1, hi1);
            ull ssum;
            ADD2(ssum, pack2(lo0, lo1), pack2(hi0, hi1));
            float s0, s1; unpack2(ssum, s0, s1);
            float p0 = ex2f(s0), p1 = ex2f(s1);
            ADD2(lacc, lacc, pack2(p0, p1));
            ull pp0 = pack2(p0, p0), pp1 = pack2(p1, p1);
            FMA2(o[0][0], pp0, va.x, o[0][0]);
            FMA2(o[0][1], pp0, va.y, o[0][1]);
            FMA2(o[0][2], pp0, vb.x, o[0][2]);
            FMA2(o[0][3], pp0, vb.y, o[0][3]);
            FMA2(o[0][4], pp0, vc.x, o[0][4]);
            FMA2(o[0][5], pp0, vc.y, o[0][5]);
            FMA2(o[0][6], pp0, vd.x, o[0][6]);
            FMA2(o[0][7], pp0, vd.y, o[0][7]);
            FMA2(o[1][0], pp1, va.x, o[1][0]);
            FMA2(o[1][1], pp1, va.y, o[1][1]);
            FMA2(o[1][2], pp1, vb.x, o[1][2]);
            FMA2(o[1][3], pp1, vb.y, o[1][3]);
            FMA2(o[1][4], pp1, vc.x, o[1][4]);
            FMA2(o[1][5], pp1, vc.y, o[1][5]);
            FMA2(o[1][6], pp1, vd.x, o[1][6]);
            FMA2(o[1][7], pp1, vd.y, o[1][7]);
        }
    }

    // merge partials into global accumulators
    float l0, l1; unpack2(lacc, l0, l1);
#pragma unroll
    for (int r = 0; r < 2; r++) {
        float* op = g_oAcc + (((size_t)(b * N_ + n0 + r)) * 4 + head) * 16;
        float ov[16];
#pragma unroll
        for (int j = 0; j < 8; j++) unpack2(o[r][j], ov[2*j], ov[2*j+1]);
#pragma unroll
        for (int d = 0; d < 16; d++) atomicAdd(op + d, ov[d]);
        atomicAdd(&g_lAcc[(b * N_ + n0 + r) * 4 + head], r == 0 ? l0 : l1);
    }
}

// ---------------- kernel 2b: attention epilogue ----------------
__global__ __launch_bounds__(256) void attn_epi(const float* __restrict__ v_gains) {
    int b = blockIdx.y;
    int t = threadIdx.x;
    int n = blockIdx.x * 256 + t;
    __shared__ float sW[8][16];
    float gain = 0.25f * v_gains[0];
    float att[16];
#pragma unroll
    for (int d = 0; d < 16; d++) att[d] = 0.f;
#pragma unroll
    for (int h = 0; h < 4; h++) {
        float inv = rcpf(g_lAcc[(b * N_ + n) * 4 + h]);
        const float4* op = (const float4*)(g_oAcc + (((size_t)(b * N_ + n)) * 4 + h) * 16);
#pragma unroll
        for (int i = 0; i < 4; i++) {
            float4 v = op[i];
            att[4*i]   = fmaf(v.x, inv, att[4*i]);
            att[4*i+1] = fmaf(v.y, inv, att[4*i+1]);
            att[4*i+2] = fmaf(v.z, inv, att[4*i+2]);
            att[4*i+3] = fmaf(v.w, inv, att[4*i+3]);
        }
    }
#pragma unroll
    for (int d = 0; d < 16; d++) att[d] *= gain;
    float4* ap = (float4*)(g_att + ((size_t)b * N_ + n) * 16);
#pragma unroll
    for (int i = 0; i < 4; i++)
        ap[i] = make_float4(att[4*i], att[4*i+1], att[4*i+2], att[4*i+3]);
    float w[16];
#pragma unroll
    for (int d = 0; d < 16; d++) {
        float v = att[d];
        v += __shfl_xor_sync(0xffffffffu, v, 1);
        v += __shfl_xor_sync(0xffffffffu, v, 2);
        v += __shfl_xor_sync(0xffffffffu, v, 4);
        v += __shfl_xor_sync(0xffffffffu, v, 8);
        v += __shfl_xor_sync(0xffffffffu, v, 16);
        w[d] = v;
    }
    if ((t & 31) == 0) {
#pragma unroll
        for (int d = 0; d < 16; d++) sW[t >> 5][d] = w[d];
    }
    __syncthreads();
    if (t < 16) {
        float s = 0.f;
#pragma unroll
        for (int ww = 0; ww < 8; ww++) s += sW[ww][t];
        atomicAdd(&g_wsumAcc[b * 16 + t], s);
    }
}

// ---------------- kernel 3: candidates + fim partials ----------------
__global__ __launch_bounds__(256) void cand_kernel(const float* __restrict__ W_act,
                            const float* __restrict__ b_act) {
    int b = blockIdx.z, k = blockIdx.y, ch = blockIdx.x;
    __shared__ __align__(16) float W[16][16];
    __shared__ __align__(16) float bias[16];
    int t = threadIdx.x;
    W[t >> 4][t & 15] = W_act[(k * 16 + (t >> 4)) * 16 + (t & 15)];
    if (t < 16) bias[t] = b_act[k * 16 + t] + g_hypf[(b * K_ + k) * 16 + t];
    __syncthreads();
    int n = ch * 256 + t;
    float a[16];
    const float4* ap = (const float4*)(g_att + ((size_t)b * N_ + n) * 16);
#pragma unroll
    for (int i = 0; i < 4; i++) { float4 v = ap[i]; a[4*i]=v.x; a[4*i+1]=v.y; a[4*i+2]=v.z; a[4*i+3]=v.w; }
    ull ad[16];
#pragma unroll
    for (int d = 0; d < 16; d++) ad[d] = pack2(a[d], a[d]);
    float c[16], ss = 0.f;
#pragma unroll
    for (int e2 = 0; e2 < 8; e2++) {
        ull acc = ((const ull*)bias)[e2];
#pragma unroll
        for (int d = 0; d < 16; d++) FMA2(acc, ad[d], ((const ull*)&W[d][0])[e2], acc);
        float v0, v1; unpack2(acc, v0, v1);
        v0 = fast_tanh(v0); v1 = fast_tanh(v1);
        c[2*e2] = v0; c[2*e2+1] = v1;
        ss = fmaf(v0, v0, fmaf(v1, v1, ss));
    }
    float4* cp = (float4*)(g_cand + (((size_t)(b * K_ + k)) * N_ + n) * 16);
#pragma unroll
    for (int i = 0; i < 4; i++) cp[i] = make_float4(c[4*i], c[4*i+1], c[4*i+2], c[4*i+3]);
    ss *= (1.f / 16.f);
#pragma unroll
    for (int off = 16; off > 0; off >>= 1) ss += __shfl_xor_sync(0xffffffffu, ss, off);
    __shared__ float wsums[8];
    if ((t & 31) == 0) wsums[t >> 5] = ss;
    __syncthreads();
    if (t == 0) {
        float tot = 0.f;
#pragma unroll
        for (int i = 0; i < 8; i++) tot += wsums[i];
        atomicAdd(&g_fimraw[b * K_ + k], tot);
    }
}

// ---------------- kernel 4: fused small-math + weighted select + gates + norm ----------------
__global__ __launch_bounds__(256) void final_kernel(const float* __restrict__ state,
                            const float* __restrict__ hyp, const float* __restrict__ R_accum,
                            const float* __restrict__ W_ws, const float* __restrict__ b_ws,
                            const float* __restrict__ W_s1, const float* __restrict__ b_s1,
                            const float* __restrict__ W_s2, const float* __restrict__ b_s2,
                            const float* __restrict__ W_lift, const float* __restrict__ b_lift,
                            const float* __restrict__ rotors,
                            const float* __restrict__ Wg1, const float* __restrict__ bg1,
                            const float* __restrict__ Wg2, const float* __restrict__ bg2,
                            const float* __restrict__ Wc1, const float* __restrict__ bc1,
                            const float* __restrict__ Wc2, const float* __restrict__ bc2,
                            const float* __restrict__ norm_scale,
                            float* __restrict__ out_ns, float* __restrict__ out_newhyp,
                            float* __restrict__ out_R, float* __restrict__ out_fim,
                            float* __restrict__ out_w, float* __restrict__ out_gate) {
    int b = blockIdx.y;
    int bx = blockIdx.x;
    int t = threadIdx.x;
    int n = bx * 256 + t;

    __shared__ __align__(16) float sWg1[32][64];
    __shared__ __align__(16) float sWg2[64][16];
    __shared__ __align__(16) float sbg1[64], sbg2[16];
    __shared__ float sWc1[2][16], sbc1[16], sWc2[16], sns[16];
    __shared__ float sW1[640], sW2[320];
    __shared__ float sC[256];
    __shared__ float s_nh[8][4], s_logit[8], s_fim[8];
    __shared__ float s_w[8], s_agg[4], s_mod[16];
    __shared__ float s_Rt[16], s_Racc[16], s_Rn[16];
    __shared__ float sbc2, s_g0;

    for (int i = t; i < 2048; i += 256) sWg1[i >> 6][i & 63] = Wg1[i];
    for (int i = t; i < 1024; i += 256) sWg2[i >> 4][i & 15] = Wg2[i];
    for (int i = t; i < 640; i += 256) sW1[i] = W_s1[i];
    for (int i = t; i < 320; i += 256) sW2[i] = W_s2[i];
    sC[t] = cayley_sign(t >> 4, t & 15);
    if (t < 64) sbg1[t] = bg1[t];
    if (t < 16) { sbg2[t] = bg2[t]; sbc1[t] = bc1[t]; sWc2[t] = Wc2[t]; sns[t] = norm_scale[t]; }
    if (t < 32) sWc1[t >> 4][t & 15] = Wc1[t];
    if (t == 0) sbc2 = bc2[0];
    __syncthreads();

    const float invN = 1.f / (float)N_;
    if (t < 32) {
        int p = t >> 2;
        int q = t & 3;
        float fim = g_fimraw[b * 8 + p] * invN;
        float feat[10];
#pragma unroll
        for (int c = 0; c < 4; c++) feat[c] = hyp[(b * 8 + p) * 4 + c];
#pragma unroll
        for (int c = 0; c < 4; c++) {
            float v = b_ws[c];
#pragma unroll
            for (int d = 0; d < 16; d++)
                v = fmaf(g_wsumAcc[b * 16 + d] * invN, W_ws[d * 4 + c], v);
            feat[4 + c] = v;
        }
        feat[8] = fim; feat[9] = fim;
        float sp[5] = {0.f, 0.f, 0.f, 0.f, 0.f};
        for (int j = q; j < 64; j += 4) {
            float h = b_s1[j];
#pragma unroll
            for (int i = 0; i < 10; i++) h = fmaf(feat[i], sW1[i * 64 + j], h);
            h = fmaxf(h, 0.f);
#pragma unroll
            for (int c = 0; c < 5; c++) sp[c] = fmaf(h, sW2[j * 5 + c], sp[c]);
        }
#pragma unroll
        for (int c = 0; c < 5; c++) {
            sp[c] += __shfl_xor_sync(0xffffffffu, sp[c], 1);
            sp[c] += __shfl_xor_sync(0xffffffffu, sp[c], 2);
        }
        if (q == 0) {
            s_fim[p] = fim;
#pragma unroll
            for (int c = 0; c < 4; c++) s_nh[p][c] = feat[c] + sp[c] + b_s2[c];
            s_logit[p] = sp[4] + b_s2[4];
        }
        __syncwarp();
        if (t == 0) {
            float mx = -1e30f;
#pragma unroll
            for (int k = 0; k < 8; k++) mx = fmaxf(mx, s_logit[k]);
            float e[8], se = 0.f;
#pragma unroll
            for (int k = 0; k < 8; k++) { e[k] = __expf(s_logit[k] - mx); se += e[k]; }
            float inv = 1.f / se;
            float agg[4] = {0.f, 0.f, 0.f, 0.f};
#pragma unroll
            for (int k = 0; k < 8; k++) {
                float w = e[k] * inv;
                s_w[k] = w;
#pragma unroll
                for (int c = 0; c < 4; c++) agg[c] = fmaf(w, s_nh[k][c], agg[c]);
            }
#pragma unroll
            for (int c = 0; c < 4; c++) s_agg[c] = agg[c];
        }
        __syncwarp();
        if (t < 16) {
            float v = b_lift[t];
#pragma unroll
            for (int c = 0; c < 4; c++) v = fmaf(s_agg[c], W_lift[c * 16 + t], v);
            s_mod[t] = 1.f + tanhf(v);
        }
    }
    __syncthreads();

    if (bx == 0) {
        if (t < 8) { out_fim[b * 8 + t] = s_fim[t]; out_w[b * 8 + t] = s_w[t]; }
        if (t < 32) out_newhyp[b * 32 + t] = s_nh[t >> 2][t & 3];
        if (t < 16) {
            float v = 0.f;
#pragma unroll
            for (int k = 0; k < 8; k++) v = fmaf(s_w[k], rotors[k * 16 + t], v);
            s_Rt[t] = v;
            s_Racc[t] = R_accum[b * 16 + t];
        }
    }
    __syncthreads();
    if (bx == 0 && t < 16) {
        float v = 0.f;
#pragma unroll
        for (int a = 0; a < 16; a++) {
            int bb = a ^ t;
            v = fmaf(sC[a * 16 + bb] * s_Rt[a], s_Racc[bb], v);
        }
        s_Rn[t] = v;
    }
    __syncthreads();
    if (bx == 0 && t == 0) {
        float g0 = 0.f;
#pragma unroll
        for (int a = 0; a < 16; a++)
            g0 += sC[a * 16 + a] * s_Rn[a] * s_Rn[a] * rev_sign(a);
        s_g0 = rsqrtf(fmaxf(fabsf(g0), 1e-6f));
    }
    __syncthreads();
    if (bx == 0 && t < 16) out_R[b * 16 + t] = s_Rn[t] * s_g0;

    float in[32];
    const float4* sp = (const float4*)(state + ((size_t)b * N_ + n) * 16);
#pragma unroll
    for (int i = 0; i < 4; i++) { float4 v = sp[i]; in[4*i]=v.x; in[4*i+1]=v.y; in[4*i+2]=v.z; in[4*i+3]=v.w; }

    float ns_[16];
#pragma unroll
    for (int e = 0; e < 16; e++) ns_[e] = 0.f;
#pragma unroll
    for (int k = 0; k < 8; k++) {
        const float4* cp = (const float4*)(g_cand + (((size_t)(b * K_ + k)) * N_ + n) * 16);
        float wk = s_w[k];
#pragma unroll
        for (int i = 0; i < 4; i++) {
            float4 v = cp[i];
            ns_[4*i]   = fmaf(wk, v.x, ns_[4*i]);
            ns_[4*i+1] = fmaf(wk, v.y, ns_[4*i+1]);
            ns_[4*i+2] = fmaf(wk, v.z, ns_[4*i+2]);
            ns_[4*i+3] = fmaf(wk, v.w, ns_[4*i+3]);
        }
    }
#pragma unroll
    for (int e = 0; e < 16; e++) { ns_[e] *= s_mod[e]; in[16 + e] = ns_[e]; }

    ull accE[8];
#pragma unroll
    for (int e2 = 0; e2 < 8; e2++) accE[e2] = ((const ull*)sbg2)[e2];
#pragma unroll
    for (int half = 0; half < 2; half++) {
        ull accH[16];
#pragma unroll
        for (int j2 = 0; j2 < 16; j2++) accH[j2] = ((const ull*)sbg1)[half * 16 + j2];
#pragma unroll
        for (int i = 0; i < 32; i++) {
            ull ind = pack2(in[i], in[i]);
            const ull* wrow = (const ull*)&sWg1[i][half * 32];
#pragma unroll
            for (int j2 = 0; j2 < 16; j2++) FMA2(accH[j2], ind, wrow[j2], accH[j2]);
        }
#pragma unroll
        for (int j2 = 0; j2 < 16; j2++) {
            float h0, h1; unpack2(accH[j2], h0, h1);
            h0 = fmaxf(h0, 0.f); h1 = fmaxf(h1, 0.f);
            int j = half * 32 + j2 * 2;
            ull hd0 = pack2(h0, h0), hd1 = pack2(h1, h1);
            const ull* w0 = (const ull*)&sWg2[j][0];
            const ull* w1 = (const ull*)&sWg2[j + 1][0];
#pragma unroll
            for (int e2 = 0; e2 < 8; e2++) {
                FMA2(accE[e2], hd0, w0[e2], accE[e2]);
                FMA2(accE[e2], hd1, w1[e2], accE[e2]);
            }
        }
    }
    float gate[16];
#pragma unroll
    for (int e2 = 0; e2 < 8; e2++) {
        float a0, a1; unpack2(accE[e2], a0, a1);
        gate[2*e2]   = rcpf(1.f + ex2f(-LOG2E_ * a0));
        gate[2*e2+1] = rcpf(1.f + ex2f(-LOG2E_ * a1));
    }

    float cg = sbc2;
#pragma unroll
    for (int j = 0; j < 16; j++) {
        float h = fmaf(in[0], sWc1[0][j], fmaf(ns_[0], sWc1[1][j], sbc1[j]));
        h = fmaxf(h, 0.f);
        cg = fmaf(h, sWc2[j], cg);
    }
    cg = rcpf(1.f + ex2f(-LOG2E_ * cg));

    float val[16];
    val[0] = cg * ns_[0] + (1.f - cg) * in[0];
#pragma unroll
    for (int d = 1; d < 16; d++) val[d] = gate[d] * ns_[d] + (1.f - gate[d]) * in[d];

    float ms = 0.f;
#pragma unroll
    for (int d = 0; d < 16; d++) ms = fmaf(val[d], val[d], ms);
    float r = rsqrtf(ms * (1.f / 16.f) + 1e-6f);

    float4* no = (float4*)(out_ns + ((size_t)b * N_ + n) * 16);
    float4* go = (float4*)(out_gate + ((size_t)b * N_ + n) * 16);
#pragma unroll
    for (int i = 0; i < 4; i++) {
        no[i] = make_float4(val[4*i] * sns[4*i] * r, val[4*i+1] * sns[4*i+1] * r,
                            val[4*i+2] * sns[4*i+2] * r, val[4*i+3] * sns[4*i+3] * r);
        go[i] = make_float4(gate[4*i], gate[4*i+1], gate[4*i+2], gate[4*i+3]);
    }
}

// ---------------- launch ----------------
extern "C" void kernel_launch(void* const* d_in, const int* in_sizes, int n_in,
                              void* d_out, int out_size) {
    const float* state   = (const float*)d_in[0];
    const float* hyp     = (const float*)d_in[1];
    const float* R_accum = (const float*)d_in[2];
    const float* Wq = (const float*)d_in[4];
    const float* bq = (const float*)d_in[5];
    const float* Wk = (const float*)d_in[6];
    const float* bk = (const float*)d_in[7];
    const float* v_gains = (const float*)d_in[8];
    const float* W_act = (const float*)d_in[9];
    const float* b_act = (const float*)d_in[10];
    const float* W_hyp = (const float*)d_in[11];
    const float* b_hyp = (const float*)d_in[12];
    const float* W_ws = (const float*)d_in[13];
    const float* b_ws = (const float*)d_in[14];
    const float* W_s1 = (const float*)d_in[15];
    const float* b_s1 = (const float*)d_in[16];
    const float* W_s2 = (const float*)d_in[17];
    const float* b_s2 = (const float*)d_in[18];
    const float* W_lift = (const float*)d_in[19];
    const float* b_lift = (const float*)d_in[20];
    const float* Wg1 = (const float*)d_in[21];
    const float* bg1 = (const float*)d_in[22];
    const float* Wg2 = (const float*)d_in[23];
    const float* bg2 = (const float*)d_in[24];
    const float* Wc1 = (const float*)d_in[25];
    const float* bc1 = (const float*)d_in[26];
    const float* Wc2 = (const float*)d_in[27];
    const float* bc2 = (const float*)d_in[28];
    const float* norm_scale = (const float*)d_in[29];
    const float* rotors = (const float*)d_in[30];

    float* out = (float*)d_out;
    float* out_ns     = out;
    float* out_newhyp = out + (size_t)B_ * N_ * D_;
    float* out_R      = out_newhyp + B_ * K_ * 4;
    float* out_fim    = out_R + B_ * 16;
    float* out_w      = out_fim + B_ * K_;
    float* out_gate   = out_w + B_ * K_;

    proj_kernel<<<(B_ * N_) / 128, 128>>>(state, Wq, bq, Wk, bk, hyp, W_hyp, b_hyp);
    attn_kernel<<<dim3(N_ / 128, B_, MSPLIT_), 256>>>(state);
    attn_epi<<<dim3(N_ / 256, B_), 256>>>(v_gains);
    cand_kernel<<<dim3(N_ / 256, K_, B_), 256>>>(W_act, b_act);
    final_kernel<<<dim3(N_ / 256, B_), 256>>>(state, hyp, R_accum, W_ws, b_ws,
                                              W_s1, b_s1, W_s2, b_s2, W_lift, b_lift, rotors,
                                              Wg1, bg1, Wg2, bg2, Wc1, bc1, Wc2, bc2, norm_scale,
                                              out_ns, out_newhyp, out_R, out_fim, out_w, out_gate);
}